// round 10
// baseline (speedup 1.0000x reference)
#include <cuda_runtime.h>

#define NP   4096   // particle capacity
#define NCX  8      // 8^3 cells of size 2R
#define NC   512
#define CAP  96     // slots per cell (mean ~33 for this data)

static constexpr float R_      = 0.1f;
static constexpr float DT_     = 1.0f / 60.0f;
static constexpr float MAXV    = 3.0f;                 // 0.5*0.1/DT
static constexpr float RHO0    = 17510.1f;
static constexpr float STIFF   = 2.99e-11f;
static constexpr float SPIKY   = 4.774648292756860e6f; // 15/(pi*R^6)
static constexpr float NSPIKY3 = -3.0f * 4.774648292756860e6f;
static constexpr float VDTR    = 60.0f * (1.0f / 60.0f) / 17510.1f; // VISC*DT/RHO0
static constexpr float EPS_    = 1e-8f;
// self-pair contribution to rho: d_self = sqrt(EPS) = 1e-4, t = R - 1e-4
static constexpr float W_SELF  =
    (float)(4.774648292756860e6 * 0.0999 * 0.0999 * 0.0999);

// ---------------- scratch (device globals: allocation-guard safe) -----------
__device__ float  g_px[NP], g_py[NP], g_pz[NP];   // current pred (orig order)
__device__ float  g_lam[NP];
__device__ float  g_nvx[NP], g_nvy[NP], g_nvz[NP];
__device__ int    g_cnt[4][NC];                   // per-grid cell counts (zero-init)
__device__ float4 g_slot[4][NC * CAP];            // pos.xyz + (lambda in .w)
__device__ int    g_sidx[4][NP];                  // particle -> slot index
__device__ float4 g_nvslot[NC * CAP];             // new_vel, slot-parallel (grid 3)

// ---------------- cell helpers (cell size = 2R = 0.2) -----------------------
__device__ __forceinline__ int clampi(int v) { return min(max(v, 0), NCX - 1); }
__device__ __forceinline__ int ccell(float x) {          // insertion cell
    return clampi(__float2int_rd(x * 5.0f) + 1);
}
__device__ __forceinline__ int cbase(float x) {          // probe low cell
    return clampi(__float2int_rd(x * 5.0f - 0.5f) + 1);
}
__device__ __forceinline__ int bidx3(int ix, int iy, int iz) {
    return ix | (iy << 3) | (iz << 6);
}
__device__ __forceinline__ int grid_insert(int g, float x, float y, float z) {
    int h = bidx3(ccell(x), ccell(y), ccell(z));
    int s = atomicAdd(&g_cnt[g][h], 1);
    if (s >= CAP) return -1;                // effectively unreachable
    int si = h * CAP + s;
    g_slot[g][si] = make_float4(x, y, z, 0.0f);
    return si;
}

// 64 lanes per particle: cell = t64&7 (2x2x2 probe), sublane = t64>>3 (0..7)
// returns bucket h; lane scans t = sub, sub+8, sub+16, ...
__device__ __forceinline__ int probe64(int t64, float px, float py, float pz) {
    int ix = cbase(px) + (t64 & 1);
    int iy = cbase(py) + ((t64 >> 1) & 1);
    int iz = cbase(pz) + ((t64 >> 2) & 1);
    return bidx3(ix, iy, iz);
}

// warp-reduce helper
__device__ __forceinline__ float wred(float v) {
#pragma unroll
    for (int o = 16; o; o >>= 1) v += __shfl_xor_sync(0xffffffffu, v, o);
    return v;
}

// ---------------------------------------------------------------------------
// 1) external forces + cap + predicted positions; insert into grid 0
//    (cnt[0] was zeroed by previous call's k_xsph; first call: static init)
// ---------------------------------------------------------------------------
__global__ void k_predict(const float* __restrict__ locs,
                          const float* __restrict__ vel, int N) {
    int i = blockIdx.x * blockDim.x + threadIdx.x;
    if (i >= N) return;
    float vx = vel[3 * i + 0];
    float vy = vel[3 * i + 1] - 9.8f * DT_;
    float vz = vel[3 * i + 2];
    float nrm = sqrtf(vx * vx + vy * vy + vz * vz);
    float s = fminf(MAXV / (nrm + 1e-4f), 1.0f);
    float px = locs[3 * i + 0] + DT_ * vx * s;
    float py = locs[3 * i + 1] + DT_ * vy * s;
    float pz = locs[3 * i + 2] + DT_ * vz * s;
    g_px[i] = px; g_py[i] = py; g_pz[i] = pz;
    g_sidx[0][i] = grid_insert(0, px, py, pz);
}

// ---------------------------------------------------------------------------
// 2) lambda: 64 lanes / particle, 4 particles / 256-thr block (1024 blocks)
//    block 0 also zeroes cnt[g+1] (not read until a later launch)
// ---------------------------------------------------------------------------
__global__ void __launch_bounds__(256) k_lambda(int g, int N) {
    __shared__ int   s_cnt[NC];
    __shared__ float s_red[4];
    int tid = threadIdx.x;
    if (blockIdx.x == 0) {
        for (int k = tid; k < NC; k += 256) g_cnt[g + 1][k] = 0;
    }
    for (int k = tid; k < NC; k += 256) s_cnt[k] = min(g_cnt[g][k], CAP);
    if (tid < 4) s_red[tid] = 0.0f;
    __syncthreads();

    int pslot = tid >> 6;               // particle within block (0..3)
    int p     = blockIdx.x * 4 + pslot;
    int t64   = tid & 63;
    int lane  = tid & 31;

    float pxi = g_px[p], pyi = g_py[p], pzi = g_pz[p];
    int h   = probe64(t64, pxi, pyi, pzi);
    int sub = t64 >> 3;                 // 0..7
    int n   = s_cnt[h];
    const float4* __restrict__ base = g_slot[g] + h * CAP;

    float acc = 0.0f;
#define LBODY(S) { \
        float dx = pxi - (S).x, dy = pyi - (S).y, dz = pzi - (S).z;          \
        float d2 = dx * dx + dy * dy + dz * dz + EPS_;                       \
        float rinv = rsqrtf(d2);                                             \
        float d = d2 * rinv;                                                 \
        float tt = fmaxf(R_ - d, 0.0f);                                      \
        acc += (SPIKY * tt) * (tt * tt); }
    int t = sub;
    for (; t + 8 < n; t += 16) {        // paired independent loads (MLP 2)
        float4 s0 = __ldg(base + t);
        float4 s1 = __ldg(base + t + 8);
        LBODY(s0); LBODY(s1);
    }
    if (t < n) { float4 s0 = __ldg(base + t); LBODY(s0); }
#undef LBODY

    acc = wred(acc);
    if (lane == 0) atomicAdd(&s_red[pslot], acc);
    __syncthreads();
    if (t64 == 0) {
        float lam = -((s_red[pslot] - W_SELF) - RHO0) * STIFF;
        g_lam[p] = lam;
        int si = g_sidx[g][p];
        if (si >= 0) g_slot[g][si].w = lam;   // pack lambda into slot.w
    }
}

// ---------------------------------------------------------------------------
// 3) delta: pred += sum (lam_i+lam_j)*dw/d*diff; insert into grid g+1.
//    doFinal: new_vel + nv slots + emit pred to out
// ---------------------------------------------------------------------------
__global__ void __launch_bounds__(256) k_delta(int g, const float* __restrict__ locs,
                                               float* __restrict__ out,
                                               int doFinal, int N) {
    __shared__ int   s_cnt[NC];
    __shared__ float s_red[4][3];
    int tid = threadIdx.x;
    for (int k = tid; k < NC; k += 256) s_cnt[k] = min(g_cnt[g][k], CAP);
    if (tid < 12) ((float*)s_red)[tid] = 0.0f;
    __syncthreads();

    int pslot = tid >> 6;
    int p     = blockIdx.x * 4 + pslot;
    int t64   = tid & 63;
    int lane  = tid & 31;

    float pxi = g_px[p], pyi = g_py[p], pzi = g_pz[p];
    float li  = g_lam[p];
    int h   = probe64(t64, pxi, pyi, pzi);
    int sub = t64 >> 3;
    int n   = s_cnt[h];
    const float4* __restrict__ base = g_slot[g] + h * CAP;

    float ax = 0.0f, ay = 0.0f, az = 0.0f;
#define DBODY(S) { \
        float dx = pxi - (S).x, dy = pyi - (S).y, dz = pzi - (S).z;          \
        float d2 = dx * dx + dy * dy + dz * dz + EPS_;                       \
        float rinv = rsqrtf(d2);                                             \
        float d = d2 * rinv;                                                 \
        float tt = fmaxf(R_ - d, 0.0f);                                      \
        float coef = (li + (S).w) * (NSPIKY3 * (tt * tt)) * rinv;            \
        ax += coef * dx; ay += coef * dy; az += coef * dz; }
    int t = sub;
    for (; t + 8 < n; t += 16) {
        float4 s0 = __ldg(base + t);
        float4 s1 = __ldg(base + t + 8);
        DBODY(s0); DBODY(s1);
    }
    if (t < n) { float4 s0 = __ldg(base + t); DBODY(s0); }
#undef DBODY

    ax = wred(ax); ay = wred(ay); az = wred(az);
    if (lane == 0) {
        atomicAdd(&s_red[pslot][0], ax);
        atomicAdd(&s_red[pslot][1], ay);
        atomicAdd(&s_red[pslot][2], az);
    }
    __syncthreads();
    if (t64 == 0) {
        float nx = pxi + s_red[pslot][0];
        float ny = pyi + s_red[pslot][1];
        float nz = pzi + s_red[pslot][2];
        g_px[p] = nx; g_py[p] = ny; g_pz[p] = nz;
        int si = grid_insert(g + 1, nx, ny, nz);
        g_sidx[g + 1][p] = si;
        if (doFinal) {
            float vx = (nx - locs[3 * p + 0]) * (1.0f / DT_);
            float vy = (ny - locs[3 * p + 1]) * (1.0f / DT_);
            float vz = (nz - locs[3 * p + 2]) * (1.0f / DT_);
            g_nvx[p] = vx; g_nvy[p] = vy; g_nvz[p] = vz;
            if (si >= 0) g_nvslot[si] = make_float4(vx, vy, vz, 0.0f);
            out[3 * p + 0] = nx;
            out[3 * p + 1] = ny;
            out[3 * p + 2] = nz;
        }
    }
}

// ---------------------------------------------------------------------------
// 4) XSPH viscosity + cap on grid 3; zero cnt[0..2] for the next call
// ---------------------------------------------------------------------------
__global__ void __launch_bounds__(256) k_xsph(float* __restrict__ out, int N) {
    const int g = 3;
    __shared__ int   s_cnt[NC];
    __shared__ float s_red[4][4];
    int tid = threadIdx.x;
    if (blockIdx.x < 3) {   // cleanup for next kernel_launch call
        for (int k = tid; k < NC; k += 256) g_cnt[blockIdx.x][k] = 0;
    }
    for (int k = tid; k < NC; k += 256) s_cnt[k] = min(g_cnt[g][k], CAP);
    if (tid < 16) ((float*)s_red)[tid] = 0.0f;
    __syncthreads();

    int pslot = tid >> 6;
    int p     = blockIdx.x * 4 + pslot;
    int t64   = tid & 63;
    int lane  = tid & 31;

    float pxi = g_px[p], pyi = g_py[p], pzi = g_pz[p];
    int h   = probe64(t64, pxi, pyi, pzi);
    int sub = t64 >> 3;
    int n   = s_cnt[h];
    const float4* __restrict__ base  = g_slot[g] + h * CAP;
    const float4* __restrict__ vbase = g_nvslot + h * CAP;

    float ws = 0.0f, wx = 0.0f, wy = 0.0f, wz = 0.0f;
#define XBODY(S, V) { \
        float dx = pxi - (S).x, dy = pyi - (S).y, dz = pzi - (S).z;          \
        float d2 = dx * dx + dy * dy + dz * dz + EPS_;                       \
        float rinv = rsqrtf(d2);                                             \
        float d = d2 * rinv;                                                 \
        float tt = fmaxf(R_ - d, 0.0f);                                      \
        float wk = (SPIKY * tt) * (tt * tt);                                 \
        ws += wk; wx += wk * (V).x; wy += wk * (V).y; wz += wk * (V).z; }
    int t = sub;
    for (; t + 8 < n; t += 16) {
        float4 s0 = __ldg(base + t);
        float4 v0 = __ldg(vbase + t);
        float4 s1 = __ldg(base + t + 8);
        float4 v1 = __ldg(vbase + t + 8);
        XBODY(s0, v0); XBODY(s1, v1);
    }
    if (t < n) {
        float4 s0 = __ldg(base + t);
        float4 v0 = __ldg(vbase + t);
        XBODY(s0, v0);
    }
#undef XBODY

    ws = wred(ws); wx = wred(wx); wy = wred(wy); wz = wred(wz);
    if (lane == 0) {
        atomicAdd(&s_red[pslot][0], ws);
        atomicAdd(&s_red[pslot][1], wx);
        atomicAdd(&s_red[pslot][2], wy);
        atomicAdd(&s_red[pslot][3], wz);
    }
    __syncthreads();
    if (t64 == 0) {
        float S = s_red[pslot][0];
        float vix = g_nvx[p], viy = g_nvy[p], viz = g_nvz[p];
        float nx = vix + VDTR * (s_red[pslot][1] - S * vix);
        float ny = viy + VDTR * (s_red[pslot][2] - S * viy);
        float nz = viz + VDTR * (s_red[pslot][3] - S * viz);
        float nrm = sqrtf(nx * nx + ny * ny + nz * nz);
        float sc = fminf(MAXV / (nrm + 1e-4f), 1.0f);
        out[3 * N + 3 * p + 0] = nx * sc;
        out[3 * N + 3 * p + 1] = ny * sc;
        out[3 * N + 3 * p + 2] = nz * sc;
    }
}

// ---------------------------------------------------------------------------
extern "C" void kernel_launch(void* const* d_in, const int* in_sizes, int n_in,
                              void* d_out, int out_size) {
    const float* locs = (const float*)d_in[0];
    const float* vel  = (const float*)d_in[1];
    float* out = (float*)d_out;
    int N = in_sizes[0] / 3;  // 4096

    const int TPB = 256;
    int eb = (N + TPB - 1) / TPB;   // elementwise blocks (16)
    int pb = N / 4;                 // 64 lanes/particle, 4 particles/block (1024)

    k_predict<<<eb, TPB>>>(locs, vel, N);
    for (int it = 0; it < 3; ++it) {
        k_lambda<<<pb, TPB>>>(it, N);
        k_delta<<<pb, TPB>>>(it, locs, out, it == 2, N);
    }
    k_xsph<<<pb, TPB>>>(out, N);
}

// round 11
// speedup vs baseline: 1.1585x; 1.1585x over previous
#include <cuda_runtime.h>

#define NP   4096   // particle capacity
#define NCX  8      // 8^3 cells of size 2R
#define NC   512
#define CAP  96     // slots per cell (mean ~33 for this data)

static constexpr float R_      = 0.1f;
static constexpr float DT_     = 1.0f / 60.0f;
static constexpr float MAXV    = 3.0f;                 // 0.5*0.1/DT
static constexpr float RHO0    = 17510.1f;
static constexpr float STIFF   = 2.99e-11f;
static constexpr float SPIKY   = 4.774648292756860e6f; // 15/(pi*R^6)
static constexpr float NSPIKY3 = -3.0f * 4.774648292756860e6f;
static constexpr float VDTR    = 60.0f * (1.0f / 60.0f) / 17510.1f; // VISC*DT/RHO0
static constexpr float EPS_    = 1e-8f;
// self-pair contribution to rho: d_self = sqrt(EPS) = 1e-4, t = R - 1e-4
static constexpr float W_SELF  =
    (float)(4.774648292756860e6 * 0.0999 * 0.0999 * 0.0999);

// ---------------- scratch (device globals: allocation-guard safe) -----------
__device__ float  g_px[NP], g_py[NP], g_pz[NP];   // current pred (orig order)
__device__ float  g_lam[NP];
__device__ float  g_nvx[NP], g_nvy[NP], g_nvz[NP];
__device__ int    g_cnt[4][NC];                   // per-grid cell counts (zero-init)
__device__ float4 g_slot[4][NC * CAP];            // pos.xyz + (lambda in .w)
__device__ int    g_sidx[4][NP];                  // particle -> slot index
__device__ float4 g_nvslot[NC * CAP];             // new_vel, slot-parallel (grid 3)

// ---------------- cell helpers (cell size = 2R = 0.2) -----------------------
__device__ __forceinline__ int clampi(int v) { return min(max(v, 0), NCX - 1); }
__device__ __forceinline__ int ccell(float x) {          // insertion cell
    return clampi(__float2int_rd(x * 5.0f) + 1);
}
__device__ __forceinline__ int cbase(float x) {          // probe low cell
    return clampi(__float2int_rd(x * 5.0f - 0.5f) + 1);
}
__device__ __forceinline__ int bidx3(int ix, int iy, int iz) {
    return ix | (iy << 3) | (iz << 6);
}
__device__ __forceinline__ int grid_insert(int g, float x, float y, float z) {
    int h = bidx3(ccell(x), ccell(y), ccell(z));
    int s = atomicAdd(&g_cnt[g][h], 1);
    if (s >= CAP) return -1;                // effectively unreachable
    int si = h * CAP + s;
    g_slot[g][si] = make_float4(x, y, z, 0.0f);
    return si;
}

// warp-reduce helper
__device__ __forceinline__ float wred(float v) {
#pragma unroll
    for (int o = 16; o; o >>= 1) v += __shfl_xor_sync(0xffffffffu, v, o);
    return v;
}

// common probe setup: 2 warps/particle; this warp's 4 buckets (coalesced scan)
struct Probe4 {
    int n[4];
    const float4* base[4];
    int si4[4];                 // h*CAP (for secondary arrays)
};
__device__ __forceinline__ Probe4 probe_setup(const int* s_cnt, int g,
                                              float px, float py, float pz,
                                              int half) {
    Probe4 pr;
    int bx = cbase(px), by = cbase(py), bz = cbase(pz) + half;
#pragma unroll
    for (int k = 0; k < 4; ++k) {
        int h = bidx3(bx + (k & 1), by + ((k >> 1) & 1), bz);
        pr.n[k] = s_cnt[h];
        pr.si4[k] = h * CAP;
        pr.base[k] = g_slot[g] + h * CAP;
    }
    return pr;
}

// ---------------------------------------------------------------------------
// 1) external forces + cap + predicted positions; insert into grid 0
//    (cnt[0] zeroed by previous call's k_xsph; first call: static zero-init)
// ---------------------------------------------------------------------------
__global__ void k_predict(const float* __restrict__ locs,
                          const float* __restrict__ vel, int N) {
    int i = blockIdx.x * blockDim.x + threadIdx.x;
    if (i >= N) return;
    float vx = vel[3 * i + 0];
    float vy = vel[3 * i + 1] - 9.8f * DT_;
    float vz = vel[3 * i + 2];
    float nrm = sqrtf(vx * vx + vy * vy + vz * vz);
    float s = fminf(MAXV / (nrm + 1e-4f), 1.0f);
    float px = locs[3 * i + 0] + DT_ * vx * s;
    float py = locs[3 * i + 1] + DT_ * vy * s;
    float pz = locs[3 * i + 2] + DT_ * vz * s;
    g_px[i] = px; g_py[i] = py; g_pz[i] = pz;
    g_sidx[0][i] = grid_insert(0, px, py, pz);
}

// ---------------------------------------------------------------------------
// 2) lambda: 2 warps/particle, 4 buckets/warp, lane-coalesced bucket scan
// ---------------------------------------------------------------------------
__global__ void __launch_bounds__(256) k_lambda(int g, int N) {
    __shared__ int   s_cnt[NC];
    __shared__ float s_red[4];
    int tid = threadIdx.x;
    if (blockIdx.x == 0) {      // zero next grid's counters (read later only)
        for (int k = tid; k < NC; k += 256) g_cnt[g + 1][k] = 0;
    }
    for (int k = tid; k < NC; k += 256) s_cnt[k] = min(g_cnt[g][k], CAP);
    if (tid < 4) s_red[tid] = 0.0f;
    __syncthreads();

    int pslot = tid >> 6;               // particle within block (0..3)
    int p     = blockIdx.x * 4 + pslot;
    int t64   = tid & 63;
    int half  = t64 >> 5;               // which warp of the pair
    int lane  = tid & 31;

    float pxi = g_px[p], pyi = g_py[p], pzi = g_pz[p];
    Probe4 pr = probe_setup(s_cnt, g, pxi, pyi, pzi, half);

    float acc = 0.0f;
#define LBODY(S) { \
        float dx = pxi - (S).x, dy = pyi - (S).y, dz = pzi - (S).z;          \
        float d2 = dx * dx + dy * dy + dz * dz + EPS_;                       \
        float rinv = rsqrtf(d2);                                             \
        float d = d2 * rinv;                                                 \
        float tt = fmaxf(R_ - d, 0.0f);                                      \
        acc += (SPIKY * tt) * (tt * tt); }

    float4 buf[4];
#pragma unroll
    for (int k = 0; k < 4; ++k)         // 4 independent coalesced loads
        if (lane < pr.n[k]) buf[k] = __ldg(pr.base[k] + lane);
#pragma unroll
    for (int k = 0; k < 4; ++k)
        if (lane < pr.n[k]) LBODY(buf[k]);
#pragma unroll
    for (int k = 0; k < 4; ++k)         // overflow (n>32), still coalesced
        for (int t = 32 + lane; t < pr.n[k]; t += 32) {
            float4 s = __ldg(pr.base[k] + t);
            LBODY(s);
        }
#undef LBODY

    acc = wred(acc);
    if (lane == 0) atomicAdd(&s_red[pslot], acc);
    __syncthreads();
    if (t64 == 0) {
        float lam = -((s_red[pslot] - W_SELF) - RHO0) * STIFF;
        g_lam[p] = lam;
        int si = g_sidx[g][p];
        if (si >= 0) g_slot[g][si].w = lam;   // pack lambda into slot.w
    }
}

// ---------------------------------------------------------------------------
// 3) delta: pred += sum (lam_i+lam_j)*dw/d*diff; insert into grid g+1.
//    doFinal: new_vel + nv slots + emit pred to out
// ---------------------------------------------------------------------------
__global__ void __launch_bounds__(256) k_delta(int g, const float* __restrict__ locs,
                                               float* __restrict__ out,
                                               int doFinal, int N) {
    __shared__ int   s_cnt[NC];
    __shared__ float s_red[4][3];
    int tid = threadIdx.x;
    for (int k = tid; k < NC; k += 256) s_cnt[k] = min(g_cnt[g][k], CAP);
    if (tid < 12) ((float*)s_red)[tid] = 0.0f;
    __syncthreads();

    int pslot = tid >> 6;
    int p     = blockIdx.x * 4 + pslot;
    int t64   = tid & 63;
    int half  = t64 >> 5;
    int lane  = tid & 31;

    float pxi = g_px[p], pyi = g_py[p], pzi = g_pz[p];
    float li  = g_lam[p];
    Probe4 pr = probe_setup(s_cnt, g, pxi, pyi, pzi, half);

    float ax = 0.0f, ay = 0.0f, az = 0.0f;
#define DBODY(S) { \
        float dx = pxi - (S).x, dy = pyi - (S).y, dz = pzi - (S).z;          \
        float d2 = dx * dx + dy * dy + dz * dz + EPS_;                       \
        float rinv = rsqrtf(d2);                                             \
        float d = d2 * rinv;                                                 \
        float tt = fmaxf(R_ - d, 0.0f);                                      \
        float coef = (li + (S).w) * (NSPIKY3 * (tt * tt)) * rinv;            \
        ax += coef * dx; ay += coef * dy; az += coef * dz; }

    float4 buf[4];
#pragma unroll
    for (int k = 0; k < 4; ++k)
        if (lane < pr.n[k]) buf[k] = __ldg(pr.base[k] + lane);
#pragma unroll
    for (int k = 0; k < 4; ++k)
        if (lane < pr.n[k]) DBODY(buf[k]);
#pragma unroll
    for (int k = 0; k < 4; ++k)
        for (int t = 32 + lane; t < pr.n[k]; t += 32) {
            float4 s = __ldg(pr.base[k] + t);
            DBODY(s);
        }
#undef DBODY

    ax = wred(ax); ay = wred(ay); az = wred(az);
    if (lane == 0) {
        atomicAdd(&s_red[pslot][0], ax);
        atomicAdd(&s_red[pslot][1], ay);
        atomicAdd(&s_red[pslot][2], az);
    }
    __syncthreads();
    if (t64 == 0) {
        float nx = pxi + s_red[pslot][0];
        float ny = pyi + s_red[pslot][1];
        float nz = pzi + s_red[pslot][2];
        g_px[p] = nx; g_py[p] = ny; g_pz[p] = nz;
        int si = grid_insert(g + 1, nx, ny, nz);
        g_sidx[g + 1][p] = si;
        if (doFinal) {
            float vx = (nx - locs[3 * p + 0]) * (1.0f / DT_);
            float vy = (ny - locs[3 * p + 1]) * (1.0f / DT_);
            float vz = (nz - locs[3 * p + 2]) * (1.0f / DT_);
            g_nvx[p] = vx; g_nvy[p] = vy; g_nvz[p] = vz;
            if (si >= 0) g_nvslot[si] = make_float4(vx, vy, vz, 0.0f);
            out[3 * p + 0] = nx;
            out[3 * p + 1] = ny;
            out[3 * p + 2] = nz;
        }
    }
}

// ---------------------------------------------------------------------------
// 4) XSPH viscosity + cap on grid 3; zero cnt[0..2] for the next call
// ---------------------------------------------------------------------------
__global__ void __launch_bounds__(256) k_xsph(float* __restrict__ out, int N) {
    const int g = 3;
    __shared__ int   s_cnt[NC];
    __shared__ float s_red[4][4];
    int tid = threadIdx.x;
    if (blockIdx.x < 3) {   // cleanup for next kernel_launch call
        for (int k = tid; k < NC; k += 256) g_cnt[blockIdx.x][k] = 0;
    }
    for (int k = tid; k < NC; k += 256) s_cnt[k] = min(g_cnt[g][k], CAP);
    if (tid < 16) ((float*)s_red)[tid] = 0.0f;
    __syncthreads();

    int pslot = tid >> 6;
    int p     = blockIdx.x * 4 + pslot;
    int t64   = tid & 63;
    int half  = t64 >> 5;
    int lane  = tid & 31;

    float pxi = g_px[p], pyi = g_py[p], pzi = g_pz[p];
    Probe4 pr = probe_setup(s_cnt, g, pxi, pyi, pzi, half);

    float ws = 0.0f, wx = 0.0f, wy = 0.0f, wz = 0.0f;
#define XBODY(S, V) { \
        float dx = pxi - (S).x, dy = pyi - (S).y, dz = pzi - (S).z;          \
        float d2 = dx * dx + dy * dy + dz * dz + EPS_;                       \
        float rinv = rsqrtf(d2);                                             \
        float d = d2 * rinv;                                                 \
        float tt = fmaxf(R_ - d, 0.0f);                                      \
        float wk = (SPIKY * tt) * (tt * tt);                                 \
        ws += wk; wx += wk * (V).x; wy += wk * (V).y; wz += wk * (V).z; }

    float4 buf[4], vbuf[4];
#pragma unroll
    for (int k = 0; k < 4; ++k)
        if (lane < pr.n[k]) {
            buf[k]  = __ldg(pr.base[k] + lane);
            vbuf[k] = __ldg(g_nvslot + pr.si4[k] + lane);
        }
#pragma unroll
    for (int k = 0; k < 4; ++k)
        if (lane < pr.n[k]) XBODY(buf[k], vbuf[k]);
#pragma unroll
    for (int k = 0; k < 4; ++k)
        for (int t = 32 + lane; t < pr.n[k]; t += 32) {
            float4 s = __ldg(pr.base[k] + t);
            float4 v = __ldg(g_nvslot + pr.si4[k] + t);
            XBODY(s, v);
        }
#undef XBODY

    ws = wred(ws); wx = wred(wx); wy = wred(wy); wz = wred(wz);
    if (lane == 0) {
        atomicAdd(&s_red[pslot][0], ws);
        atomicAdd(&s_red[pslot][1], wx);
        atomicAdd(&s_red[pslot][2], wy);
        atomicAdd(&s_red[pslot][3], wz);
    }
    __syncthreads();
    if (t64 == 0) {
        float S = s_red[pslot][0];
        float vix = g_nvx[p], viy = g_nvy[p], viz = g_nvz[p];
        float nx = vix + VDTR * (s_red[pslot][1] - S * vix);
        float ny = viy + VDTR * (s_red[pslot][2] - S * viy);
        float nz = viz + VDTR * (s_red[pslot][3] - S * viz);
        float nrm = sqrtf(nx * nx + ny * ny + nz * nz);
        float sc = fminf(MAXV / (nrm + 1e-4f), 1.0f);
        out[3 * N + 3 * p + 0] = nx * sc;
        out[3 * N + 3 * p + 1] = ny * sc;
        out[3 * N + 3 * p + 2] = nz * sc;
    }
}

// ---------------------------------------------------------------------------
extern "C" void kernel_launch(void* const* d_in, const int* in_sizes, int n_in,
                              void* d_out, int out_size) {
    const float* locs = (const float*)d_in[0];
    const float* vel  = (const float*)d_in[1];
    float* out = (float*)d_out;
    int N = in_sizes[0] / 3;  // 4096

    const int TPB = 256;
    int eb = (N + TPB - 1) / TPB;   // elementwise blocks (16)
    int pb = N / 4;                 // 4 particles/block, 2 warps each (1024)

    k_predict<<<eb, TPB>>>(locs, vel, N);
    for (int it = 0; it < 3; ++it) {
        k_lambda<<<pb, TPB>>>(it, N);
        k_delta<<<pb, TPB>>>(it, locs, out, it == 2, N);
    }
    k_xsph<<<pb, TPB>>>(out, N);
}